// round 2
// baseline (speedup 1.0000x reference)
#include <cuda_runtime.h>
#include <cuda_bf16.h>
#include <cstdint>

// ============================================================================
// BitLinear on GB300 (compute_103 base target — no tcgen05 / no "a" features):
//   out[m,n] = s[m] * wscale * sum_k q[m,k] * t[n,k]
//   q = clip(rint(x/s), -8, 7)  (int8, bit-exact vs reference)
//   t = clip(rint(w/ws), -1, 1) (int8, bit-exact vs reference)
// int8 mma.sync GEMM with exact s32 accumulation, fp32 epilogue scaling.
// ============================================================================

#define DIM_M 8192
#define DIM_N 16384
#define DIM_K 4096

#define BM 128
#define BN 128
#define BK 64
#define NK (DIM_K / BK)        // 64 chunks
#define STAGES 4

#define ROWB 80                 // smem bytes per 64B row (16B pad: conflict-free)
#define A_ST (BM * ROWB)        // 10240
#define ST_BYTES (2 * BM * ROWB) // 20480 per stage
#define GEMM_SMEM (STAGES * ST_BYTES)
#define GEMM_THREADS 256

// ---------------- device globals (static scratch; allocation-free) ----------
__device__ __align__(1024) int8_t g_Xq[(size_t)DIM_M * DIM_K];  // 32 MB
__device__ __align__(1024) int8_t g_Wq[(size_t)DIM_N * DIM_K];  // 64 MB
__device__ float g_Xs[DIM_M];
__device__ float g_partial[2048];
__device__ float g_wscale;

// ---------------- helpers ----------------------------------------------------
__device__ __forceinline__ uint32_t smem_u32(const void* p) {
    uint32_t a;
    asm("{ .reg .u64 t; cvta.to.shared.u64 t, %1; cvt.u32.u64 %0, t; }" : "=r"(a) : "l"(p));
    return a;
}

__device__ __forceinline__ void cp_async16(uint32_t dst, const void* src) {
    unsigned long long g = (unsigned long long)__cvta_generic_to_global(src);
    asm volatile("cp.async.cg.shared.global [%0], [%1], 16;" :: "r"(dst), "l"(g) : "memory");
}
__device__ __forceinline__ void cp_commit() {
    asm volatile("cp.async.commit_group;" ::: "memory");
}
template <int N>
__device__ __forceinline__ void cp_wait() {
    asm volatile("cp.async.wait_group %0;" :: "n"(N) : "memory");
}

__device__ __forceinline__ void ldsm_x4(uint32_t (&r)[4], uint32_t addr) {
    asm volatile("ldmatrix.sync.aligned.m8n8.x4.shared.b16 {%0,%1,%2,%3}, [%4];"
                 : "=r"(r[0]), "=r"(r[1]), "=r"(r[2]), "=r"(r[3]) : "r"(addr));
}

__device__ __forceinline__ void mma_s8(int (&d)[4], const uint32_t (&a)[4],
                                       uint32_t b0, uint32_t b1) {
    asm volatile(
        "mma.sync.aligned.m16n8k32.row.col.s32.s8.s8.s32 "
        "{%0,%1,%2,%3}, {%4,%5,%6,%7}, {%8,%9}, {%0,%1,%2,%3};"
        : "+r"(d[0]), "+r"(d[1]), "+r"(d[2]), "+r"(d[3])
        : "r"(a[0]), "r"(a[1]), "r"(a[2]), "r"(a[3]), "r"(b0), "r"(b1));
}

// ============================================================================
// Kernel 1: partial |W| sums (deterministic fixed order)
// ============================================================================
__global__ void __launch_bounds__(256) wabs_partial(const float* __restrict__ w) {
    const int tid = threadIdx.x;
    const float4* w4 = reinterpret_cast<const float4*>(w);
    const size_t total4 = (size_t)DIM_N * DIM_K / 4;
    float s = 0.0f;
    for (size_t i = (size_t)blockIdx.x * blockDim.x + tid; i < total4;
         i += (size_t)gridDim.x * blockDim.x) {
        float4 v = w4[i];
        s += fabsf(v.x) + fabsf(v.y) + fabsf(v.z) + fabsf(v.w);
    }
    #pragma unroll
    for (int o = 16; o; o >>= 1) s += __shfl_xor_sync(0xFFFFFFFFu, s, o);
    __shared__ float sm[8];
    if ((tid & 31) == 0) sm[tid >> 5] = s;
    __syncthreads();
    if (tid == 0) {
        float t = 0.0f;
        #pragma unroll
        for (int i = 0; i < 8; i++) t += sm[i];
        g_partial[blockIdx.x] = t;
    }
}

__global__ void __launch_bounds__(256) wscale_finalize() {
    const int tid = threadIdx.x;
    float s = 0.0f;
    for (int i = tid; i < 2048; i += 256) s += g_partial[i];
    #pragma unroll
    for (int o = 16; o; o >>= 1) s += __shfl_xor_sync(0xFFFFFFFFu, s, o);
    __shared__ float sm[8];
    if ((tid & 31) == 0) sm[tid >> 5] = s;
    __syncthreads();
    if (tid == 0) {
        float t = 0.0f;
        #pragma unroll
        for (int i = 0; i < 8; i++) t += sm[i];
        float mean = t * (1.0f / 67108864.0f);   // exact /2^26
        g_wscale = fmaxf(mean, 1e-5f);
    }
}

// ============================================================================
// Kernel 3: ternary W -> int8 {-1,0,+1}; exact vs clip(rint(w/ws),-1,1)
// ============================================================================
__global__ void __launch_bounds__(256) quant_w_kernel(const float* __restrict__ w) {
    const size_t i4 = (size_t)blockIdx.x * 256 + threadIdx.x;
    const float ws = g_wscale;
    const float half = 0.5f * ws;          // exact (power-of-2 scale)
    const float band = half * 1.000001f;
    float4 v = reinterpret_cast<const float4*>(w)[i4];
    int t[4];
    float e[4] = {v.x, v.y, v.z, v.w};
    #pragma unroll
    for (int j = 0; j < 4; j++) {
        float aw = fabsf(e[j]);
        int tv = (aw > half) ? 1 : 0;
        if (tv && aw < band) {
            // only mismatch zone: true ratio just above 0.5 but fl(aw/ws)==0.5
            tv = (int)fminf(rintf(__fdiv_rn(aw, ws)), 1.0f);
        }
        t[j] = (e[j] < 0.0f) ? -tv : tv;
    }
    uint32_t pk = (uint32_t)(t[0] & 0xFF) | ((uint32_t)(t[1] & 0xFF) << 8) |
                  ((uint32_t)(t[2] & 0xFF) << 16) | ((uint32_t)t[3] << 24);
    reinterpret_cast<uint32_t*>(g_Wq)[i4] = pk;
}

// ============================================================================
// Kernel 4: per-token int4 activation quant -> int8 in [-8,7] + scale
// ============================================================================
__device__ __forceinline__ int q_int4(float x, float s) {
    float d = __fdividef(x, s);            // <=2 ulp approx
    float r = rintf(d);
    if (fabsf(d - r) > 0.4995f)            // near tie: resolve with exact rn div
        r = rintf(__fdiv_rn(x, s));
    r = fminf(fmaxf(r, -8.0f), 7.0f);
    return (int)r;
}

__global__ void __launch_bounds__(256) quant_x_kernel(const float* __restrict__ x) {
    const int token = blockIdx.x;
    const int tid = threadIdx.x;
    const float4* row = reinterpret_cast<const float4*>(x + (size_t)token * DIM_K);
    float4 v[4];
    float am = 0.0f;
    #pragma unroll
    for (int i = 0; i < 4; i++) {
        v[i] = row[tid + 256 * i];
        am = fmaxf(am, fmaxf(fmaxf(fabsf(v[i].x), fabsf(v[i].y)),
                             fmaxf(fabsf(v[i].z), fabsf(v[i].w))));
    }
    #pragma unroll
    for (int o = 16; o; o >>= 1) am = fmaxf(am, __shfl_xor_sync(0xFFFFFFFFu, am, o));
    __shared__ float sm[8];
    __shared__ float s_bcast;
    if ((tid & 31) == 0) sm[tid >> 5] = am;
    __syncthreads();
    if (tid == 0) {
        float t = sm[0];
        #pragma unroll
        for (int i = 1; i < 8; i++) t = fmaxf(t, sm[i]);
        float s = __fdiv_rn(fmaxf(t, 1e-5f), 7.0f);   // match jnp x/7.0 exactly
        s_bcast = s;
        g_Xs[token] = s;
    }
    __syncthreads();
    const float s = s_bcast;
    uint32_t* orow = reinterpret_cast<uint32_t*>(g_Xq + (size_t)token * DIM_K);
    #pragma unroll
    for (int i = 0; i < 4; i++) {
        int a = q_int4(v[i].x, s), b = q_int4(v[i].y, s);
        int c = q_int4(v[i].z, s), d = q_int4(v[i].w, s);
        uint32_t pk = (uint32_t)(a & 0xFF) | ((uint32_t)(b & 0xFF) << 8) |
                      ((uint32_t)(c & 0xFF) << 16) | ((uint32_t)d << 24);
        orow[tid + 256 * i] = pk;
    }
}

// ============================================================================
// Kernel 5: int8 GEMM via mma.sync.m16n8k32, 128x128x64 tiles, 4-stage cp.async
// ============================================================================
__device__ __forceinline__ void load_tile(uint32_t dstbase, int m0, int n0,
                                          int chunk, int tid) {
    const int k0 = chunk * BK;
    #pragma unroll
    for (int i = 0; i < 2; i++) {
        int seg = tid + i * 256;
        int r = seg >> 2, c = seg & 3;
        cp_async16(dstbase + r * ROWB + c * 16,
                   g_Xq + (size_t)(m0 + r) * DIM_K + k0 + c * 16);
    }
    #pragma unroll
    for (int i = 0; i < 2; i++) {
        int seg = tid + i * 256;
        int r = seg >> 2, c = seg & 3;
        cp_async16(dstbase + A_ST + r * ROWB + c * 16,
                   g_Wq + (size_t)(n0 + r) * DIM_K + k0 + c * 16);
    }
}

__global__ void __launch_bounds__(GEMM_THREADS, 2) bitlinear_gemm(float* __restrict__ out) {
    extern __shared__ char smem_raw[];
    const uint32_t sb = smem_u32(smem_raw);

    const int tid = threadIdx.x;
    const int lane = tid & 31;
    const int wid = tid >> 5;
    const int wm = wid & 1;            // 2 warps along M
    const int wn = wid >> 1;           // 4 warps along N

    // tile mapping: groups of 8 M-tiles sweep all 128 N-tiles (L2 reuse of A slab)
    const int bid = blockIdx.x;
    const int g = bid >> 10;           // / (8*128)
    const int r = bid & 1023;
    const int m0 = (g * 8 + (r & 7)) * BM;
    const int n0 = (r >> 3) * BN;

    // smem fragment base offsets (16B aligned; ROWB=80 stride is conflict-free)
    const uint32_t a_row_off = (uint32_t)((wm * 64 + (lane & 15)) * ROWB + (lane >> 4) * 16);
    const uint32_t b_row_off = (uint32_t)(A_ST + (wn * 32 + lane) * ROWB);

    int acc[4][4][4];
    #pragma unroll
    for (int i = 0; i < 4; i++)
        #pragma unroll
        for (int j = 0; j < 4; j++)
            #pragma unroll
            for (int k = 0; k < 4; k++) acc[i][j][k] = 0;

    // prologue: stages 0..STAGES-2 in flight
    #pragma unroll
    for (int s = 0; s < STAGES - 1; s++) {
        load_tile(sb + s * ST_BYTES, m0, n0, s, tid);
        cp_commit();
    }

    for (int kc = 0; kc < NK; kc++) {
        cp_wait<STAGES - 2>();
        __syncthreads();

        // issue next stage (wrapped chunk index keeps commit cadence uniform;
        // wrapped loads land in stages that are never read again)
        load_tile(sb + ((kc + STAGES - 1) & (STAGES - 1)) * ST_BYTES,
                  m0, n0, (kc + STAGES - 1) & (NK - 1), tid);
        cp_commit();

        const uint32_t sbase = sb + (uint32_t)(kc & (STAGES - 1)) * ST_BYTES;
        const uint32_t a_base = sbase + a_row_off;
        const uint32_t b_base = sbase + b_row_off;

        #pragma unroll
        for (int ksi = 0; ksi < 2; ksi++) {
            uint32_t af[4][4];
            #pragma unroll
            for (int mf = 0; mf < 4; mf++)
                ldsm_x4(af[mf], a_base + mf * (16 * ROWB) + ksi * 32);
            uint32_t bf0[4], bf1[4];
            ldsm_x4(bf0, b_base + ksi * 32);
            ldsm_x4(bf1, b_base + ksi * 32 + 16);
            #pragma unroll
            for (int mf = 0; mf < 4; mf++)
                #pragma unroll
                for (int nf = 0; nf < 4; nf++)
                    mma_s8(acc[mf][nf], af[mf], bf0[nf], bf1[nf]);
        }
    }

    // ---------------- epilogue: scale by s[m]*wscale, write fp32 -------------
    const float ws = g_wscale;
    const int m_base = m0 + wm * 64;
    const int n_base = n0 + wn * 32;
    const int lr = lane >> 2, lc = lane & 3;

    #pragma unroll
    for (int mf = 0; mf < 4; mf++) {
        const int r0 = m_base + mf * 16 + lr;
        const float s0 = g_Xs[r0] * ws;
        const float s1 = g_Xs[r0 + 8] * ws;
        float* p0 = out + (size_t)r0 * DIM_N + n_base + 2 * lc;
        float* p1 = p0 + (size_t)8 * DIM_N;
        #pragma unroll
        for (int nf = 0; nf < 4; nf++) {
            float2 v0, v1;
            v0.x = __int2float_rn(acc[mf][nf][0]) * s0;
            v0.y = __int2float_rn(acc[mf][nf][1]) * s0;
            v1.x = __int2float_rn(acc[mf][nf][2]) * s1;
            v1.y = __int2float_rn(acc[mf][nf][3]) * s1;
            *reinterpret_cast<float2*>(p0 + nf * 8) = v0;
            *reinterpret_cast<float2*>(p1 + nf * 8) = v1;
        }
    }
}

// ============================================================================
extern "C" void kernel_launch(void* const* d_in, const int* in_sizes, int n_in,
                              void* d_out, int out_size) {
    const float* x = (const float*)d_in[0];   // (4, 2048, 4096) fp32
    const float* w = (const float*)d_in[1];   // (16384, 4096) fp32
    float* out = (float*)d_out;               // (4, 2048, 16384) fp32
    (void)in_sizes; (void)n_in; (void)out_size;

    cudaFuncSetAttribute(bitlinear_gemm, cudaFuncAttributeMaxDynamicSharedMemorySize, GEMM_SMEM);

    wabs_partial<<<2048, 256>>>(w);
    wscale_finalize<<<1, 256>>>();
    quant_w_kernel<<<(int)(((size_t)DIM_N * DIM_K) / 1024), 256>>>(w);
    quant_x_kernel<<<DIM_M, 256>>>(x);

    const int grid = (DIM_M / BM) * (DIM_N / BN);  // 64 * 128 = 8192
    bitlinear_gemm<<<grid, GEMM_THREADS, GEMM_SMEM>>>(out);
}

// round 3
// speedup vs baseline: 1.0282x; 1.0282x over previous
#include <cuda_runtime.h>
#include <cuda_bf16.h>
#include <cstdint>

// ============================================================================
// BitLinear on GB300 (compute_103 base target — legacy mma.sync path):
//   out[m,n] = s[m] * wscale * sum_k q[m,k] * t[n,k]
//   q = clip(rint(x/s), -8, 7)  (int8)
//   t = clip(rint(w/ws), -1, 1) (int8)
// int8 mma.sync m16n8k32 GEMM, exact s32 accumulation, fp32 epilogue.
// 4 launches total so ncu (-s 5 -c 1, 2 harness launches ahead) captures GEMM.
// ============================================================================

#define DIM_M 8192
#define DIM_N 16384
#define DIM_K 4096

#define BM 128
#define BN 256
#define BK 64
#define NK (DIM_K / BK)          // 64 chunks
#define STAGES 4

#define ROWB 80                  // 64B row + 16B pad: ldmatrix conflict-free
#define A_ST (BM * ROWB)         // 10240
#define B_ST (BN * ROWB)         // 20480
#define ST_BYTES (A_ST + B_ST)   // 30720
#define GEMM_SMEM (STAGES * ST_BYTES)   // 122880
#define GEMM_THREADS 512

// ---------------- device globals (static scratch; allocation-free) ----------
__device__ __align__(1024) int8_t g_Xq[(size_t)DIM_M * DIM_K];  // 32 MB
__device__ __align__(1024) int8_t g_Wq[(size_t)DIM_N * DIM_K];  // 64 MB
__device__ float g_Xs[DIM_M];
__device__ float g_partial[2048];
__device__ float g_wscale;

// ---------------- helpers ----------------------------------------------------
__device__ __forceinline__ uint32_t smem_u32(const void* p) {
    uint32_t a;
    asm("{ .reg .u64 t; cvta.to.shared.u64 t, %1; cvt.u32.u64 %0, t; }" : "=r"(a) : "l"(p));
    return a;
}

__device__ __forceinline__ void cp_async16(uint32_t dst, const void* src) {
    unsigned long long g = (unsigned long long)__cvta_generic_to_global(src);
    asm volatile("cp.async.cg.shared.global [%0], [%1], 16;" :: "r"(dst), "l"(g) : "memory");
}
__device__ __forceinline__ void cp_commit() {
    asm volatile("cp.async.commit_group;" ::: "memory");
}
template <int N>
__device__ __forceinline__ void cp_wait() {
    asm volatile("cp.async.wait_group %0;" :: "n"(N) : "memory");
}

__device__ __forceinline__ void ldsm_x4(uint32_t (&r)[4], uint32_t addr) {
    asm volatile("ldmatrix.sync.aligned.m8n8.x4.shared.b16 {%0,%1,%2,%3}, [%4];"
                 : "=r"(r[0]), "=r"(r[1]), "=r"(r[2]), "=r"(r[3]) : "r"(addr));
}

__device__ __forceinline__ void mma_s8(int (&d)[4], const uint32_t (&a)[4],
                                       uint32_t b0, uint32_t b1) {
    asm volatile(
        "mma.sync.aligned.m16n8k32.row.col.s32.s8.s8.s32 "
        "{%0,%1,%2,%3}, {%4,%5,%6,%7}, {%8,%9}, {%0,%1,%2,%3};"
        : "+r"(d[0]), "+r"(d[1]), "+r"(d[2]), "+r"(d[3])
        : "r"(a[0]), "r"(a[1]), "r"(a[2]), "r"(a[3]), "r"(b0), "r"(b1));
}

// ============================================================================
// Kernel 1: partial |W| sums (deterministic fixed order)
// ============================================================================
__global__ void __launch_bounds__(256) wabs_partial(const float* __restrict__ w) {
    const int tid = threadIdx.x;
    const float4* w4 = reinterpret_cast<const float4*>(w);
    const size_t total4 = (size_t)DIM_N * DIM_K / 4;
    float s = 0.0f;
    for (size_t i = (size_t)blockIdx.x * blockDim.x + tid; i < total4;
         i += (size_t)gridDim.x * blockDim.x) {
        float4 v = w4[i];
        s += fabsf(v.x) + fabsf(v.y) + fabsf(v.z) + fabsf(v.w);
    }
    #pragma unroll
    for (int o = 16; o; o >>= 1) s += __shfl_xor_sync(0xFFFFFFFFu, s, o);
    __shared__ float sm[8];
    if ((tid & 31) == 0) sm[tid >> 5] = s;
    __syncthreads();
    if (tid == 0) {
        float t = 0.0f;
        #pragma unroll
        for (int i = 0; i < 8; i++) t += sm[i];
        g_partial[blockIdx.x] = t;
    }
}

__global__ void __launch_bounds__(256) wscale_finalize() {
    const int tid = threadIdx.x;
    float s = 0.0f;
    for (int i = tid; i < 2048; i += 256) s += g_partial[i];
    #pragma unroll
    for (int o = 16; o; o >>= 1) s += __shfl_xor_sync(0xFFFFFFFFu, s, o);
    __shared__ float sm[8];
    if ((tid & 31) == 0) sm[tid >> 5] = s;
    __syncthreads();
    if (tid == 0) {
        float t = 0.0f;
        #pragma unroll
        for (int i = 0; i < 8; i++) t += sm[i];
        float mean = t * (1.0f / 67108864.0f);   // exact /2^26
        g_wscale = fmaxf(mean, 1e-5f);
    }
}

// ============================================================================
// Kernel 2 (fused): blocks [0, 65536) quantize W; blocks [65536, 73728) quant X
// ============================================================================
__device__ __forceinline__ int q_int4(float x, float s) {
    float d = __fdividef(x, s);            // <=2 ulp approx
    float r = rintf(d);
    if (fabsf(d - r) > 0.4995f)            // near tie: resolve with exact rn div
        r = rintf(__fdiv_rn(x, s));
    r = fminf(fmaxf(r, -8.0f), 7.0f);
    return (int)r;
}

#define WQ_BLOCKS 65536

__global__ void __launch_bounds__(256) quant_wx_kernel(const float* __restrict__ w,
                                                       const float* __restrict__ x) {
    const int tid = threadIdx.x;
    if (blockIdx.x < WQ_BLOCKS) {
        // ---- W: ternary {-1,0,+1}, exact vs clip(rint(w/ws),-1,1) ----
        const size_t i4 = (size_t)blockIdx.x * 256 + tid;
        const float ws = g_wscale;
        const float half = 0.5f * ws;
        const float band = half * 1.000001f;
        float4 v = reinterpret_cast<const float4*>(w)[i4];
        int t[4];
        float e[4] = {v.x, v.y, v.z, v.w};
        #pragma unroll
        for (int j = 0; j < 4; j++) {
            float aw = fabsf(e[j]);
            int tv = (aw > half) ? 1 : 0;
            if (tv && aw < band)
                tv = (int)fminf(rintf(__fdiv_rn(aw, ws)), 1.0f);
            t[j] = (e[j] < 0.0f) ? -tv : tv;
        }
        uint32_t pk = (uint32_t)(t[0] & 0xFF) | ((uint32_t)(t[1] & 0xFF) << 8) |
                      ((uint32_t)(t[2] & 0xFF) << 16) | ((uint32_t)t[3] << 24);
        reinterpret_cast<uint32_t*>(g_Wq)[i4] = pk;
    } else {
        // ---- X: per-token int4 absmax quant ----
        const int token = blockIdx.x - WQ_BLOCKS;
        const float4* row = reinterpret_cast<const float4*>(x + (size_t)token * DIM_K);
        float4 v[4];
        float am = 0.0f;
        #pragma unroll
        for (int i = 0; i < 4; i++) {
            v[i] = row[tid + 256 * i];
            am = fmaxf(am, fmaxf(fmaxf(fabsf(v[i].x), fabsf(v[i].y)),
                                 fmaxf(fabsf(v[i].z), fabsf(v[i].w))));
        }
        #pragma unroll
        for (int o = 16; o; o >>= 1) am = fmaxf(am, __shfl_xor_sync(0xFFFFFFFFu, am, o));
        __shared__ float sm[8];
        __shared__ float s_bcast;
        if ((tid & 31) == 0) sm[tid >> 5] = am;
        __syncthreads();
        if (tid == 0) {
            float t = sm[0];
            #pragma unroll
            for (int i = 1; i < 8; i++) t = fmaxf(t, sm[i]);
            float s = __fdiv_rn(fmaxf(t, 1e-5f), 7.0f);
            s_bcast = s;
            g_Xs[token] = s;
        }
        __syncthreads();
        const float s = s_bcast;
        uint32_t* orow = reinterpret_cast<uint32_t*>(g_Xq + (size_t)token * DIM_K);
        #pragma unroll
        for (int i = 0; i < 4; i++) {
            int a = q_int4(v[i].x, s), b = q_int4(v[i].y, s);
            int c = q_int4(v[i].z, s), d = q_int4(v[i].w, s);
            uint32_t pk = (uint32_t)(a & 0xFF) | ((uint32_t)(b & 0xFF) << 8) |
                          ((uint32_t)(c & 0xFF) << 16) | ((uint32_t)d << 24);
            orow[tid + 256 * i] = pk;
        }
    }
}

// ============================================================================
// Kernel 3: int8 GEMM 128x256x64 tiles, 512 threads, 4-stage cp.async
// ============================================================================
__device__ __forceinline__ void load_tile(uint32_t dstbase, int m0, int n0,
                                          int chunk, int tid) {
    const int k0 = chunk * BK;
    // A: 128 rows x 64B = 512 segs of 16B; 512 threads -> 1 each
    {
        int r = tid >> 2, c = tid & 3;
        cp_async16(dstbase + r * ROWB + c * 16,
                   g_Xq + (size_t)(m0 + r) * DIM_K + k0 + c * 16);
    }
    // B: 256 rows x 64B = 1024 segs; 2 each
    #pragma unroll
    for (int i = 0; i < 2; i++) {
        int seg = tid + i * 512;
        int r = seg >> 2, c = seg & 3;
        cp_async16(dstbase + A_ST + r * ROWB + c * 16,
                   g_Wq + (size_t)(n0 + r) * DIM_K + k0 + c * 16);
    }
}

__global__ void __launch_bounds__(GEMM_THREADS, 1) bitlinear_gemm(float* __restrict__ out) {
    extern __shared__ char smem_raw[];
    const uint32_t sb = smem_u32(smem_raw);

    const int tid = threadIdx.x;
    const int lane = tid & 31;
    const int wid = tid >> 5;
    const int wm = wid & 1;            // 2 warps along M (64 rows each)
    const int wn = wid >> 1;           // 8 warps along N (32 cols each)

    // tile mapping: groups of 8 M-tiles sweep all 64 N-tiles (A slab L2-resident)
    const int bid = blockIdx.x;
    const int g = bid >> 9;            // / (8*64)
    const int r = bid & 511;
    const int m0 = (g * 8 + (r & 7)) * BM;
    const int n0 = (r >> 3) * BN;

    const uint32_t a_row_off = (uint32_t)((wm * 64 + (lane & 15)) * ROWB + (lane >> 4) * 16);
    const uint32_t b_row_off = (uint32_t)(A_ST + (wn * 32 + lane) * ROWB);

    int acc[4][4][4];
    #pragma unroll
    for (int i = 0; i < 4; i++)
        #pragma unroll
        for (int j = 0; j < 4; j++)
            #pragma unroll
            for (int k = 0; k < 4; k++) acc[i][j][k] = 0;

    #pragma unroll
    for (int s = 0; s < STAGES - 1; s++) {
        load_tile(sb + s * ST_BYTES, m0, n0, s, tid);
        cp_commit();
    }

    for (int kc = 0; kc < NK; kc++) {
        cp_wait<STAGES - 2>();
        __syncthreads();

        // next stage load (wrapped tail keeps commit cadence; wrapped stages
        // are never read again)
        load_tile(sb + ((kc + STAGES - 1) & (STAGES - 1)) * ST_BYTES,
                  m0, n0, (kc + STAGES - 1) & (NK - 1), tid);
        cp_commit();

        const uint32_t sbase = sb + (uint32_t)(kc & (STAGES - 1)) * ST_BYTES;
        const uint32_t a_base = sbase + a_row_off;
        const uint32_t b_base = sbase + b_row_off;

        #pragma unroll
        for (int ksi = 0; ksi < 2; ksi++) {
            uint32_t af[4][4];
            #pragma unroll
            for (int mf = 0; mf < 4; mf++)
                ldsm_x4(af[mf], a_base + mf * (16 * ROWB) + ksi * 32);
            uint32_t bf0[4], bf1[4];
            ldsm_x4(bf0, b_base + ksi * 32);
            ldsm_x4(bf1, b_base + ksi * 32 + 16);
            #pragma unroll
            for (int mf = 0; mf < 4; mf++)
                #pragma unroll
                for (int nf = 0; nf < 4; nf++)
                    mma_s8(acc[mf][nf], af[mf], bf0[nf], bf1[nf]);
        }
    }

    // ---------------- epilogue: scale by s[m]*wscale, write fp32 -------------
    const float ws = g_wscale;
    const int m_base = m0 + wm * 64;
    const int n_base = n0 + wn * 32;
    const int lr = lane >> 2, lc = lane & 3;

    #pragma unroll
    for (int mf = 0; mf < 4; mf++) {
        const int r0 = m_base + mf * 16 + lr;
        const float s0 = g_Xs[r0] * ws;
        const float s1 = g_Xs[r0 + 8] * ws;
        float* p0 = out + (size_t)r0 * DIM_N + n_base + 2 * lc;
        float* p1 = p0 + (size_t)8 * DIM_N;
        #pragma unroll
        for (int nf = 0; nf < 4; nf++) {
            float2 v0, v1;
            v0.x = __int2float_rn(acc[mf][nf][0]) * s0;
            v0.y = __int2float_rn(acc[mf][nf][1]) * s0;
            v1.x = __int2float_rn(acc[mf][nf][2]) * s1;
            v1.y = __int2float_rn(acc[mf][nf][3]) * s1;
            *reinterpret_cast<float2*>(p0 + nf * 8) = v0;
            *reinterpret_cast<float2*>(p1 + nf * 8) = v1;
        }
    }
}

// ============================================================================
extern "C" void kernel_launch(void* const* d_in, const int* in_sizes, int n_in,
                              void* d_out, int out_size) {
    const float* x = (const float*)d_in[0];   // (4, 2048, 4096) fp32
    const float* w = (const float*)d_in[1];   // (16384, 4096) fp32
    float* out = (float*)d_out;               // (4, 2048, 16384) fp32
    (void)in_sizes; (void)n_in; (void)out_size;

    cudaFuncSetAttribute(bitlinear_gemm, cudaFuncAttributeMaxDynamicSharedMemorySize, GEMM_SMEM);

    wabs_partial<<<2048, 256>>>(w);
    wscale_finalize<<<1, 256>>>();
    quant_wx_kernel<<<WQ_BLOCKS + DIM_M, 256>>>(w, x);

    const int grid = (DIM_M / BM) * (DIM_N / BN);  // 64 * 64 = 4096
    bitlinear_gemm<<<grid, GEMM_THREADS, GEMM_SMEM>>>(out);
}

// round 4
// speedup vs baseline: 1.4295x; 1.3903x over previous
#include <cuda_runtime.h>
#include <cuda_bf16.h>
#include <cstdint>

// ============================================================================
// BitLinear on GB300 (compute_103 base target — legacy mma.sync + dp4a):
//   out[m,n] = s[m] * wscale * sum_k q[m,k] * t[n,k]
// Dual-pipe GEMM: warps 0-7 drive the (slow, saturated) legacy tensor pipe
// via mma.sync m16n8k32 on N cols [0,128); warps 8-15 drive the integer ALU
// pipe via dp4a on N cols [128,256). Both are exact s32 accumulation.
// ============================================================================

#define DIM_M 8192
#define DIM_N 16384
#define DIM_K 4096

#define BM 128
#define BN 256
#define BK 64
#define NK (DIM_K / BK)          // 64 chunks
#define STAGES 4

#define ROWB 80                  // 64B row + 16B pad: conflict-free
#define A_ST (BM * ROWB)         // 10240
#define B_ST (BN * ROWB)         // 20480
#define ST_BYTES (A_ST + B_ST)   // 30720
#define GEMM_SMEM (STAGES * ST_BYTES)   // 122880
#define GEMM_THREADS 512

// ---------------- device globals (static scratch; allocation-free) ----------
__device__ __align__(1024) int8_t g_Xq[(size_t)DIM_M * DIM_K];  // 32 MB
__device__ __align__(1024) int8_t g_Wq[(size_t)DIM_N * DIM_K];  // 64 MB
__device__ float g_Xs[DIM_M];
__device__ float g_partial[2048];
__device__ float g_wscale;

// ---------------- helpers ----------------------------------------------------
__device__ __forceinline__ uint32_t smem_u32(const void* p) {
    uint32_t a;
    asm("{ .reg .u64 t; cvta.to.shared.u64 t, %1; cvt.u32.u64 %0, t; }" : "=r"(a) : "l"(p));
    return a;
}

__device__ __forceinline__ void cp_async16(uint32_t dst, const void* src) {
    unsigned long long g = (unsigned long long)__cvta_generic_to_global(src);
    asm volatile("cp.async.cg.shared.global [%0], [%1], 16;" :: "r"(dst), "l"(g) : "memory");
}
__device__ __forceinline__ void cp_commit() {
    asm volatile("cp.async.commit_group;" ::: "memory");
}
template <int N>
__device__ __forceinline__ void cp_wait() {
    asm volatile("cp.async.wait_group %0;" :: "n"(N) : "memory");
}

__device__ __forceinline__ void ldsm_x4(uint32_t (&r)[4], uint32_t addr) {
    asm volatile("ldmatrix.sync.aligned.m8n8.x4.shared.b16 {%0,%1,%2,%3}, [%4];"
                 : "=r"(r[0]), "=r"(r[1]), "=r"(r[2]), "=r"(r[3]) : "r"(addr));
}

__device__ __forceinline__ void mma_s8(int (&d)[4], const uint32_t (&a)[4],
                                       uint32_t b0, uint32_t b1) {
    asm volatile(
        "mma.sync.aligned.m16n8k32.row.col.s32.s8.s8.s32 "
        "{%0,%1,%2,%3}, {%4,%5,%6,%7}, {%8,%9}, {%0,%1,%2,%3};"
        : "+r"(d[0]), "+r"(d[1]), "+r"(d[2]), "+r"(d[3])
        : "r"(a[0]), "r"(a[1]), "r"(a[2]), "r"(a[3]), "r"(b0), "r"(b1));
}

__device__ __forceinline__ void lds_v2(uint32_t& x, uint32_t& y, uint32_t addr) {
    asm volatile("ld.shared.v2.b32 {%0,%1}, [%2];" : "=r"(x), "=r"(y) : "r"(addr));
}

__device__ __forceinline__ int dp4a_(uint32_t a, uint32_t b, int c) {
    int d;
    asm("dp4a.s32.s32 %0, %1, %2, %3;" : "=r"(d) : "r"(a), "r"(b), "r"(c));
    return d;
}

// ============================================================================
// Kernel 1: partial |W| sums (deterministic fixed order)
// ============================================================================
__global__ void __launch_bounds__(256) wabs_partial(const float* __restrict__ w) {
    const int tid = threadIdx.x;
    const float4* w4 = reinterpret_cast<const float4*>(w);
    const size_t total4 = (size_t)DIM_N * DIM_K / 4;
    float s = 0.0f;
    for (size_t i = (size_t)blockIdx.x * blockDim.x + tid; i < total4;
         i += (size_t)gridDim.x * blockDim.x) {
        float4 v = w4[i];
        s += fabsf(v.x) + fabsf(v.y) + fabsf(v.z) + fabsf(v.w);
    }
    #pragma unroll
    for (int o = 16; o; o >>= 1) s += __shfl_xor_sync(0xFFFFFFFFu, s, o);
    __shared__ float sm[8];
    if ((tid & 31) == 0) sm[tid >> 5] = s;
    __syncthreads();
    if (tid == 0) {
        float t = 0.0f;
        #pragma unroll
        for (int i = 0; i < 8; i++) t += sm[i];
        g_partial[blockIdx.x] = t;
    }
}

__global__ void __launch_bounds__(256) wscale_finalize() {
    const int tid = threadIdx.x;
    float s = 0.0f;
    for (int i = tid; i < 2048; i += 256) s += g_partial[i];
    #pragma unroll
    for (int o = 16; o; o >>= 1) s += __shfl_xor_sync(0xFFFFFFFFu, s, o);
    __shared__ float sm[8];
    if ((tid & 31) == 0) sm[tid >> 5] = s;
    __syncthreads();
    if (tid == 0) {
        float t = 0.0f;
        #pragma unroll
        for (int i = 0; i < 8; i++) t += sm[i];
        float mean = t * (1.0f / 67108864.0f);   // exact /2^26
        g_wscale = fmaxf(mean, 1e-5f);
    }
}

// ============================================================================
// Kernel 2 (fused): blocks [0, 65536) quantize W; blocks [65536, 73728) quant X
// ============================================================================
__device__ __forceinline__ int q_int4(float x, float s) {
    float d = __fdividef(x, s);            // <=2 ulp approx
    float r = rintf(d);
    if (fabsf(d - r) > 0.4995f)            // near tie: resolve with exact rn div
        r = rintf(__fdiv_rn(x, s));
    r = fminf(fmaxf(r, -8.0f), 7.0f);
    return (int)r;
}

#define WQ_BLOCKS 65536

__global__ void __launch_bounds__(256) quant_wx_kernel(const float* __restrict__ w,
                                                       const float* __restrict__ x) {
    const int tid = threadIdx.x;
    if (blockIdx.x < WQ_BLOCKS) {
        const size_t i4 = (size_t)blockIdx.x * 256 + tid;
        const float ws = g_wscale;
        const float half = 0.5f * ws;
        const float band = half * 1.000001f;
        float4 v = reinterpret_cast<const float4*>(w)[i4];
        int t[4];
        float e[4] = {v.x, v.y, v.z, v.w};
        #pragma unroll
        for (int j = 0; j < 4; j++) {
            float aw = fabsf(e[j]);
            int tv = (aw > half) ? 1 : 0;
            if (tv && aw < band)
                tv = (int)fminf(rintf(__fdiv_rn(aw, ws)), 1.0f);
            t[j] = (e[j] < 0.0f) ? -tv : tv;
        }
        uint32_t pk = (uint32_t)(t[0] & 0xFF) | ((uint32_t)(t[1] & 0xFF) << 8) |
                      ((uint32_t)(t[2] & 0xFF) << 16) | ((uint32_t)t[3] << 24);
        reinterpret_cast<uint32_t*>(g_Wq)[i4] = pk;
    } else {
        const int token = blockIdx.x - WQ_BLOCKS;
        const float4* row = reinterpret_cast<const float4*>(x + (size_t)token * DIM_K);
        float4 v[4];
        float am = 0.0f;
        #pragma unroll
        for (int i = 0; i < 4; i++) {
            v[i] = row[tid + 256 * i];
            am = fmaxf(am, fmaxf(fmaxf(fabsf(v[i].x), fabsf(v[i].y)),
                                 fmaxf(fabsf(v[i].z), fabsf(v[i].w))));
        }
        #pragma unroll
        for (int o = 16; o; o >>= 1) am = fmaxf(am, __shfl_xor_sync(0xFFFFFFFFu, am, o));
        __shared__ float sm[8];
        __shared__ float s_bcast;
        if ((tid & 31) == 0) sm[tid >> 5] = am;
        __syncthreads();
        if (tid == 0) {
            float t = sm[0];
            #pragma unroll
            for (int i = 1; i < 8; i++) t = fmaxf(t, sm[i]);
            float s = __fdiv_rn(fmaxf(t, 1e-5f), 7.0f);
            s_bcast = s;
            g_Xs[token] = s;
        }
        __syncthreads();
        const float s = s_bcast;
        uint32_t* orow = reinterpret_cast<uint32_t*>(g_Xq + (size_t)token * DIM_K);
        #pragma unroll
        for (int i = 0; i < 4; i++) {
            int a = q_int4(v[i].x, s), b = q_int4(v[i].y, s);
            int c = q_int4(v[i].z, s), d = q_int4(v[i].w, s);
            uint32_t pk = (uint32_t)(a & 0xFF) | ((uint32_t)(b & 0xFF) << 8) |
                          ((uint32_t)(c & 0xFF) << 16) | ((uint32_t)d << 24);
            orow[tid + 256 * i] = pk;
        }
    }
}

// ============================================================================
// Kernel 3: dual-pipe GEMM. 128x256x64 tiles, 512 thr, 4-stage cp.async.
//   warps 0-7:  mma.sync (tensor pipe), N cols [0,128)
//   warps 8-15: dp4a     (ALU pipe),    N cols [128,256)
// ============================================================================
__device__ __forceinline__ void load_tile(uint32_t dstbase, int m0, int n0,
                                          int chunk, int tid) {
    const int k0 = chunk * BK;
    {   // A: 128 rows x 64B = 512 segs of 16B
        int r = tid >> 2, c = tid & 3;
        cp_async16(dstbase + r * ROWB + c * 16,
                   g_Xq + (size_t)(m0 + r) * DIM_K + k0 + c * 16);
    }
    #pragma unroll
    for (int i = 0; i < 2; i++) {  // B: 256 rows -> 1024 segs
        int seg = tid + i * 512;
        int r = seg >> 2, c = seg & 3;
        cp_async16(dstbase + A_ST + r * ROWB + c * 16,
                   g_Wq + (size_t)(n0 + r) * DIM_K + k0 + c * 16);
    }
}

__global__ void __launch_bounds__(GEMM_THREADS, 1) bitlinear_gemm(float* __restrict__ out) {
    extern __shared__ char smem_raw[];
    const uint32_t sb = smem_u32(smem_raw);

    const int tid = threadIdx.x;
    const int lane = tid & 31;
    const int wid = tid >> 5;
    const bool is_dp = (wid >= 8);
    const int w8 = wid & 7;
    const int wm = w8 & 1;             // 2 warps along M (64 rows each)
    const int wn = w8 >> 1;            // 4 warps along N (32 cols each)

    const int bid = blockIdx.x;
    const int g = bid >> 9;            // groups of 8 M-tiles sweep 64 N-tiles
    const int r = bid & 511;
    const int m0 = (g * 8 + (r & 7)) * BM;
    const int n0 = (r >> 3) * BN;

    // IMMA fragment offsets (cols [0,128))
    const uint32_t a_row_off = (uint32_t)((wm * 64 + (lane & 15)) * ROWB + (lane >> 4) * 16);
    const uint32_t b_row_off = (uint32_t)(A_ST + (wn * 32 + lane) * ROWB);
    // dp4a operand offsets (cols [128,256))
    const uint32_t a_dp_off = (uint32_t)((wm * 64 + (lane >> 2)) * ROWB);
    const uint32_t b_dp_off = (uint32_t)(A_ST + (128 + wn * 32 + 2 * (lane & 3)) * ROWB);

    int acc[4][4][4];
    #pragma unroll
    for (int i = 0; i < 4; i++)
        #pragma unroll
        for (int j = 0; j < 4; j++)
            #pragma unroll
            for (int k = 0; k < 4; k++) acc[i][j][k] = 0;

    #pragma unroll
    for (int s = 0; s < STAGES - 1; s++) {
        load_tile(sb + s * ST_BYTES, m0, n0, s, tid);
        cp_commit();
    }

    for (int kc = 0; kc < NK; kc++) {
        cp_wait<STAGES - 2>();
        __syncthreads();

        load_tile(sb + ((kc + STAGES - 1) & (STAGES - 1)) * ST_BYTES,
                  m0, n0, (kc + STAGES - 1) & (NK - 1), tid);
        cp_commit();

        const uint32_t sbase = sb + (uint32_t)(kc & (STAGES - 1)) * ST_BYTES;

        if (!is_dp) {
            // ---------------- tensor-pipe half ----------------
            const uint32_t a_base = sbase + a_row_off;
            const uint32_t b_base = sbase + b_row_off;
            #pragma unroll
            for (int ksi = 0; ksi < 2; ksi++) {
                uint32_t af[4][4];
                #pragma unroll
                for (int mf = 0; mf < 4; mf++)
                    ldsm_x4(af[mf], a_base + mf * (16 * ROWB) + ksi * 32);
                uint32_t bf0[4], bf1[4];
                ldsm_x4(bf0, b_base + ksi * 32);
                ldsm_x4(bf1, b_base + ksi * 32 + 16);
                #pragma unroll
                for (int mf = 0; mf < 4; mf++)
                    #pragma unroll
                    for (int nf = 0; nf < 4; nf++)
                        mma_s8(acc[mf][nf], af[mf], bf0[nf], bf1[nf]);
            }
        } else {
            // ---------------- ALU-pipe (dp4a) half ----------------
            const uint32_t a_base = sbase + a_dp_off;
            const uint32_t b_base = sbase + b_dp_off;
            #pragma unroll
            for (int kw = 0; kw < 16; kw += 2) {
                uint32_t awx[4][2], awy[4][2];   // rows 16mf + 8h + lr
                #pragma unroll
                for (int mf = 0; mf < 4; mf++)
                    #pragma unroll
                    for (int h = 0; h < 2; h++)
                        lds_v2(awx[mf][h], awy[mf][h],
                               a_base + (uint32_t)((mf * 16 + h * 8) * ROWB + kw * 4));
                uint32_t bwx[4][2], bwy[4][2];   // cols 8nf + cc + 2lc
                #pragma unroll
                for (int nf = 0; nf < 4; nf++)
                    #pragma unroll
                    for (int cc = 0; cc < 2; cc++)
                        lds_v2(bwx[nf][cc], bwy[nf][cc],
                               b_base + (uint32_t)((nf * 8 + cc) * ROWB + kw * 4));
                #pragma unroll
                for (int mf = 0; mf < 4; mf++)
                    #pragma unroll
                    for (int nf = 0; nf < 4; nf++) {
                        acc[mf][nf][0] = dp4a_(awx[mf][0], bwx[nf][0], acc[mf][nf][0]);
                        acc[mf][nf][0] = dp4a_(awy[mf][0], bwy[nf][0], acc[mf][nf][0]);
                        acc[mf][nf][1] = dp4a_(awx[mf][0], bwx[nf][1], acc[mf][nf][1]);
                        acc[mf][nf][1] = dp4a_(awy[mf][0], bwy[nf][1], acc[mf][nf][1]);
                        acc[mf][nf][2] = dp4a_(awx[mf][1], bwx[nf][0], acc[mf][nf][2]);
                        acc[mf][nf][2] = dp4a_(awy[mf][1], bwy[nf][0], acc[mf][nf][2]);
                        acc[mf][nf][3] = dp4a_(awx[mf][1], bwx[nf][1], acc[mf][nf][3]);
                        acc[mf][nf][3] = dp4a_(awy[mf][1], bwy[nf][1], acc[mf][nf][3]);
                    }
            }
        }
    }

    // ---------------- epilogue: scale by s[m]*wscale, write fp32 -------------
    const float ws = g_wscale;
    const int m_base = m0 + wm * 64;
    const int n_base = n0 + (is_dp ? 128 : 0) + wn * 32;
    const int lr = lane >> 2, lc = lane & 3;

    #pragma unroll
    for (int mf = 0; mf < 4; mf++) {
        const int r0 = m_base + mf * 16 + lr;
        const float s0 = g_Xs[r0] * ws;
        const float s1 = g_Xs[r0 + 8] * ws;
        float* p0 = out + (size_t)r0 * DIM_N + n_base + 2 * lc;
        float* p1 = p0 + (size_t)8 * DIM_N;
        #pragma unroll
        for (int nf = 0; nf < 4; nf++) {
            float2 v0, v1;
            v0.x = __int2float_rn(acc[mf][nf][0]) * s0;
            v0.y = __int2float_rn(acc[mf][nf][1]) * s0;
            v1.x = __int2float_rn(acc[mf][nf][2]) * s1;
            v1.y = __int2float_rn(acc[mf][nf][3]) * s1;
            *reinterpret_cast<float2*>(p0 + nf * 8) = v0;
            *reinterpret_cast<float2*>(p1 + nf * 8) = v1;
        }
    }
}

// ============================================================================
extern "C" void kernel_launch(void* const* d_in, const int* in_sizes, int n_in,
                              void* d_out, int out_size) {
    const float* x = (const float*)d_in[0];   // (4, 2048, 4096) fp32
    const float* w = (const float*)d_in[1];   // (16384, 4096) fp32
    float* out = (float*)d_out;               // (4, 2048, 16384) fp32
    (void)in_sizes; (void)n_in; (void)out_size;

    cudaFuncSetAttribute(bitlinear_gemm, cudaFuncAttributeMaxDynamicSharedMemorySize, GEMM_SMEM);

    wabs_partial<<<2048, 256>>>(w);
    wscale_finalize<<<1, 256>>>();
    quant_wx_kernel<<<WQ_BLOCKS + DIM_M, 256>>>(w, x);

    const int grid = (DIM_M / BM) * (DIM_N / BN);  // 64 * 64 = 4096
    bitlinear_gemm<<<grid, GEMM_THREADS, GEMM_SMEM>>>(out);
}

// round 6
// speedup vs baseline: 1.4633x; 1.0237x over previous
#include <cuda_runtime.h>
#include <cuda_bf16.h>
#include <cstdint>

// ============================================================================
// BitLinear on GB300 (compute_103 base target — legacy mma.sync + dp4a):
//   out[m,n] = s[m] * wscale * sum_k q[m,k] * t[n,k]
// Dual-pipe GEMM: warps 0-7 drive the legacy tensor pipe (mma.sync m16n8k32)
// on N cols [0,128) AND issue all cp.async tile loads; warps 8-15 drive the
// fma/ALU pipe via dp4a (v4 smem loads) on N cols [128,256).
// ============================================================================

#define DIM_M 8192
#define DIM_N 16384
#define DIM_K 4096

#define BM 128
#define BN 256
#define BK 64
#define NK (DIM_K / BK)          // 64 chunks
#define STAGES 4

#define ROWB 80                  // 64B row + 16B pad: conflict-free, 16B-aligned
#define A_ST (BM * ROWB)         // 10240
#define B_ST (BN * ROWB)         // 20480
#define ST_BYTES (A_ST + B_ST)   // 30720
#define GEMM_SMEM (STAGES * ST_BYTES)   // 122880
#define GEMM_THREADS 512

// ---------------- device globals (static scratch; allocation-free) ----------
__device__ __align__(1024) int8_t g_Xq[(size_t)DIM_M * DIM_K];  // 32 MB
__device__ __align__(1024) int8_t g_Wq[(size_t)DIM_N * DIM_K];  // 64 MB
__device__ float g_Xs[DIM_M];
__device__ float g_partial[2048];
__device__ float g_wscale;

// ---------------- helpers ----------------------------------------------------
__device__ __forceinline__ uint32_t smem_u32(const void* p) {
    uint32_t a;
    asm("{ .reg .u64 t; cvta.to.shared.u64 t, %1; cvt.u32.u64 %0, t; }" : "=r"(a) : "l"(p));
    return a;
}

__device__ __forceinline__ void cp_async16(uint32_t dst, const void* src) {
    unsigned long long g = (unsigned long long)__cvta_generic_to_global(src);
    asm volatile("cp.async.cg.shared.global [%0], [%1], 16;" :: "r"(dst), "l"(g) : "memory");
}
__device__ __forceinline__ void cp_commit() {
    asm volatile("cp.async.commit_group;" ::: "memory");
}
template <int N>
__device__ __forceinline__ void cp_wait() {
    asm volatile("cp.async.wait_group %0;" :: "n"(N) : "memory");
}

__device__ __forceinline__ void ldsm_x4(uint32_t (&r)[4], uint32_t addr) {
    asm volatile("ldmatrix.sync.aligned.m8n8.x4.shared.b16 {%0,%1,%2,%3}, [%4];"
                 : "=r"(r[0]), "=r"(r[1]), "=r"(r[2]), "=r"(r[3]) : "r"(addr));
}

__device__ __forceinline__ void mma_s8(int (&d)[4], const uint32_t (&a)[4],
                                       uint32_t b0, uint32_t b1) {
    asm volatile(
        "mma.sync.aligned.m16n8k32.row.col.s32.s8.s8.s32 "
        "{%0,%1,%2,%3}, {%4,%5,%6,%7}, {%8,%9}, {%0,%1,%2,%3};"
        : "+r"(d[0]), "+r"(d[1]), "+r"(d[2]), "+r"(d[3])
        : "r"(a[0]), "r"(a[1]), "r"(a[2]), "r"(a[3]), "r"(b0), "r"(b1));
}

__device__ __forceinline__ void lds_v4(uint32_t (&r)[4], uint32_t addr) {
    asm volatile("ld.shared.v4.b32 {%0,%1,%2,%3}, [%4];"
                 : "=r"(r[0]), "=r"(r[1]), "=r"(r[2]), "=r"(r[3]) : "r"(addr));
}

__device__ __forceinline__ int dp4a_(uint32_t a, uint32_t b, int c) {
    int d;
    asm("dp4a.s32.s32 %0, %1, %2, %3;" : "=r"(d) : "r"(a), "r"(b), "r"(c));
    return d;
}

// ============================================================================
// Kernel 1: partial |W| sums (deterministic fixed order)
// ============================================================================
__global__ void __launch_bounds__(256) wabs_partial(const float* __restrict__ w) {
    const int tid = threadIdx.x;
    const float4* w4 = reinterpret_cast<const float4*>(w);
    const size_t total4 = (size_t)DIM_N * DIM_K / 4;
    float s = 0.0f;
    for (size_t i = (size_t)blockIdx.x * blockDim.x + tid; i < total4;
         i += (size_t)gridDim.x * blockDim.x) {
        float4 v = w4[i];
        s += fabsf(v.x) + fabsf(v.y) + fabsf(v.z) + fabsf(v.w);
    }
    #pragma unroll
    for (int o = 16; o; o >>= 1) s += __shfl_xor_sync(0xFFFFFFFFu, s, o);
    __shared__ float sm[8];
    if ((tid & 31) == 0) sm[tid >> 5] = s;
    __syncthreads();
    if (tid == 0) {
        float t = 0.0f;
        #pragma unroll
        for (int i = 0; i < 8; i++) t += sm[i];
        g_partial[blockIdx.x] = t;
    }
}

__global__ void __launch_bounds__(256) wscale_finalize() {
    const int tid = threadIdx.x;
    float s = 0.0f;
    for (int i = tid; i < 2048; i += 256) s += g_partial[i];
    #pragma unroll
    for (int o = 16; o; o >>= 1) s += __shfl_xor_sync(0xFFFFFFFFu, s, o);
    __shared__ float sm[8];
    if ((tid & 31) == 0) sm[tid >> 5] = s;
    __syncthreads();
    if (tid == 0) {
        float t = 0.0f;
        #pragma unroll
        for (int i = 0; i < 8; i++) t += sm[i];
        float mean = t * (1.0f / 67108864.0f);   // exact /2^26
        g_wscale = fmaxf(mean, 1e-5f);
    }
}

// ============================================================================
// Kernel 2 (fused): blocks [0, 65536) quantize W; blocks [65536, 73728) quant X
// ============================================================================
__device__ __forceinline__ int q_int4(float x, float s) {
    float d = __fdividef(x, s);            // <=2 ulp approx
    float r = rintf(d);
    if (fabsf(d - r) > 0.4995f)            // near tie: resolve with exact rn div
        r = rintf(__fdiv_rn(x, s));
    r = fminf(fmaxf(r, -8.0f), 7.0f);
    return (int)r;
}

#define WQ_BLOCKS 65536

__global__ void __launch_bounds__(256) quant_wx_kernel(const float* __restrict__ w,
                                                       const float* __restrict__ x) {
    const int tid = threadIdx.x;
    if (blockIdx.x < WQ_BLOCKS) {
        const size_t i4 = (size_t)blockIdx.x * 256 + tid;
        const float ws = g_wscale;
        const float half = 0.5f * ws;
        const float band = half * 1.000001f;
        float4 v = reinterpret_cast<const float4*>(w)[i4];
        int t[4];
        float e[4] = {v.x, v.y, v.z, v.w};
        #pragma unroll
        for (int j = 0; j < 4; j++) {
            float aw = fabsf(e[j]);
            int tv = (aw > half) ? 1 : 0;
            if (tv && aw < band)
                tv = (int)fminf(rintf(__fdiv_rn(aw, ws)), 1.0f);
            t[j] = (e[j] < 0.0f) ? -tv : tv;
        }
        uint32_t pk = (uint32_t)(t[0] & 0xFF) | ((uint32_t)(t[1] & 0xFF) << 8) |
                      ((uint32_t)(t[2] & 0xFF) << 16) | ((uint32_t)t[3] << 24);
        reinterpret_cast<uint32_t*>(g_Wq)[i4] = pk;
    } else {
        const int token = blockIdx.x - WQ_BLOCKS;
        const float4* row = reinterpret_cast<const float4*>(x + (size_t)token * DIM_K);
        float4 v[4];
        float am = 0.0f;
        #pragma unroll
        for (int i = 0; i < 4; i++) {
            v[i] = row[tid + 256 * i];
            am = fmaxf(am, fmaxf(fmaxf(fabsf(v[i].x), fabsf(v[i].y)),
                                 fmaxf(fabsf(v[i].z), fabsf(v[i].w))));
        }
        #pragma unroll
        for (int o = 16; o; o >>= 1) am = fmaxf(am, __shfl_xor_sync(0xFFFFFFFFu, am, o));
        __shared__ float sm[8];
        __shared__ float s_bcast;
        if ((tid & 31) == 0) sm[tid >> 5] = am;
        __syncthreads();
        if (tid == 0) {
            float t = sm[0];
            #pragma unroll
            for (int i = 1; i < 8; i++) t = fmaxf(t, sm[i]);
            float s = __fdiv_rn(fmaxf(t, 1e-5f), 7.0f);
            s_bcast = s;
            g_Xs[token] = s;
        }
        __syncthreads();
        const float s = s_bcast;
        uint32_t* orow = reinterpret_cast<uint32_t*>(g_Xq + (size_t)token * DIM_K);
        #pragma unroll
        for (int i = 0; i < 4; i++) {
            int a = q_int4(v[i].x, s), b = q_int4(v[i].y, s);
            int c = q_int4(v[i].z, s), d = q_int4(v[i].w, s);
            uint32_t pk = (uint32_t)(a & 0xFF) | ((uint32_t)(b & 0xFF) << 8) |
                          ((uint32_t)(c & 0xFF) << 16) | ((uint32_t)d << 24);
            orow[tid + 256 * i] = pk;
        }
    }
}

// ============================================================================
// Kernel 3: dual-pipe GEMM. 128x256x64 tiles, 512 thr, 4-stage cp.async.
//   warps 0-7:  mma.sync (tensor pipe), N cols [0,128), and ALL cp.async loads
//   warps 8-15: dp4a (fma pipe), N cols [128,256), zero LSU-global work
// ============================================================================
__device__ __forceinline__ void load_tile(uint32_t dstbase, int m0, int n0,
                                          int chunk, int tid256) {
    // executed by threads 0..255 only (warps 0-7)
    const int k0 = chunk * BK;
    #pragma unroll
    for (int i = 0; i < 2; i++) {        // A: 128 rows x 64B = 512 segs
        int seg = tid256 + i * 256;
        int r = seg >> 2, c = seg & 3;
        cp_async16(dstbase + r * ROWB + c * 16,
                   g_Xq + (size_t)(m0 + r) * DIM_K + k0 + c * 16);
    }
    #pragma unroll
    for (int i = 0; i < 4; i++) {        // B: 256 rows -> 1024 segs
        int seg = tid256 + i * 256;
        int r = seg >> 2, c = seg & 3;
        cp_async16(dstbase + A_ST + r * ROWB + c * 16,
                   g_Wq + (size_t)(n0 + r) * DIM_K + k0 + c * 16);
    }
}

__global__ void __launch_bounds__(GEMM_THREADS, 1) bitlinear_gemm(float* __restrict__ out) {
    extern __shared__ char smem_raw[];
    const uint32_t sb = smem_u32(smem_raw);

    const int tid = threadIdx.x;
    const int lane = tid & 31;
    const int wid = tid >> 5;
    const bool is_dp = (wid >= 8);
    const int w8 = wid & 7;
    const int wm = w8 & 1;             // 2 warps along M (64 rows each)
    const int wn = w8 >> 1;            // 4 warps along N (32 cols each)

    const int bid = blockIdx.x;
    const int g = bid >> 9;            // groups of 8 M-tiles sweep 64 N-tiles
    const int r = bid & 511;
    const int m0 = (g * 8 + (r & 7)) * BM;
    const int n0 = (r >> 3) * BN;

    // IMMA fragment offsets (cols [0,128))
    const uint32_t a_row_off = (uint32_t)((wm * 64 + (lane & 15)) * ROWB + (lane >> 4) * 16);
    const uint32_t b_row_off = (uint32_t)(A_ST + (wn * 32 + lane) * ROWB);
    // dp4a operand offsets (cols [128,256))
    const uint32_t a_dp_off = (uint32_t)((wm * 64 + (lane >> 2)) * ROWB);
    const uint32_t b_dp_off = (uint32_t)(A_ST + (128 + wn * 32 + 2 * (lane & 3)) * ROWB);

    int acc[4][4][4];
    #pragma unroll
    for (int i = 0; i < 4; i++)
        #pragma unroll
        for (int j = 0; j < 4; j++)
            #pragma unroll
            for (int k = 0; k < 4; k++) acc[i][j][k] = 0;

    #pragma unroll
    for (int s = 0; s < STAGES - 1; s++) {
        if (!is_dp) load_tile(sb + s * ST_BYTES, m0, n0, s, tid);
        cp_commit();
    }

    for (int kc = 0; kc < NK; kc++) {
        cp_wait<STAGES - 2>();
        __syncthreads();

        if (!is_dp)
            load_tile(sb + ((kc + STAGES - 1) & (STAGES - 1)) * ST_BYTES,
                      m0, n0, (kc + STAGES - 1) & (NK - 1), tid);
        cp_commit();

        const uint32_t sbase = sb + (uint32_t)(kc & (STAGES - 1)) * ST_BYTES;

        if (!is_dp) {
            // ---------------- tensor-pipe half ----------------
            const uint32_t a_base = sbase + a_row_off;
            const uint32_t b_base = sbase + b_row_off;
            #pragma unroll
            for (int ksi = 0; ksi < 2; ksi++) {
                uint32_t af[4][4];
                #pragma unroll
                for (int mf = 0; mf < 4; mf++)
                    ldsm_x4(af[mf], a_base + mf * (16 * ROWB) + ksi * 32);
                uint32_t bf0[4], bf1[4];
                ldsm_x4(bf0, b_base + ksi * 32);
                ldsm_x4(bf1, b_base + ksi * 32 + 16);
                #pragma unroll
                for (int mf = 0; mf < 4; mf++)
                    #pragma unroll
                    for (int nf = 0; nf < 4; nf++)
                        mma_s8(acc[mf][nf], af[mf], bf0[nf], bf1[nf]);
            }
        } else {
            // ---------------- fma-pipe (dp4a) half, v4 loads ----------------
            const uint32_t a_base = sbase + a_dp_off;
            const uint32_t b_base = sbase + b_dp_off;
            #pragma unroll
            for (int kq = 0; kq < 4; kq++) {            // 16 k-values per iter
                uint32_t bf[4][2][4];
                #pragma unroll
                for (int nf = 0; nf < 4; nf++)
                    #pragma unroll
                    for (int cc = 0; cc < 2; cc++)
                        lds_v4(bf[nf][cc],
                               b_base + (uint32_t)((nf * 8 + cc) * ROWB + kq * 16));
                #pragma unroll
                for (int mf = 0; mf < 4; mf++) {
                    uint32_t af[2][4];
                    lds_v4(af[0], a_base + (uint32_t)((mf * 16 + 0) * ROWB + kq * 16));
                    lds_v4(af[1], a_base + (uint32_t)((mf * 16 + 8) * ROWB + kq * 16));
                    #pragma unroll
                    for (int nf = 0; nf < 4; nf++)
                        #pragma unroll
                        for (int w = 0; w < 4; w++) {
                            acc[mf][nf][0] = dp4a_(af[0][w], bf[nf][0][w], acc[mf][nf][0]);
                            acc[mf][nf][1] = dp4a_(af[0][w], bf[nf][1][w], acc[mf][nf][1]);
                            acc[mf][nf][2] = dp4a_(af[1][w], bf[nf][0][w], acc[mf][nf][2]);
                            acc[mf][nf][3] = dp4a_(af[1][w], bf[nf][1][w], acc[mf][nf][3]);
                        }
                }
            }
        }
    }

    // ---------------- epilogue: scale by s[m]*wscale, write fp32 -------------
    const float ws = g_wscale;
    const int m_base = m0 + wm * 64;
    const int n_base = n0 + (is_dp ? 128 : 0) + wn * 32;
    const int lr = lane >> 2, lc = lane & 3;

    #pragma unroll
    for (int mf = 0; mf < 4; mf++) {
        const int r0 = m_base + mf * 16 + lr;
        const float s0 = g_Xs[r0] * ws;
        const float s1 = g_Xs[r0 + 8] * ws;
        float* p0 = out + (size_t)r0 * DIM_N + n_base + 2 * lc;
        float* p1 = p0 + (size_t)8 * DIM_N;
        #pragma unroll
        for (int nf = 0; nf < 4; nf++) {
            float2 v0, v1;
            v0.x = __int2float_rn(acc[mf][nf][0]) * s0;
            v0.y = __int2float_rn(acc[mf][nf][1]) * s0;
            v1.x = __int2float_rn(acc[mf][nf][2]) * s1;
            v1.y = __int2float_rn(acc[mf][nf][3]) * s1;
            *reinterpret_cast<float2*>(p0 + nf * 8) = v0;
            *reinterpret_cast<float2*>(p1 + nf * 8) = v1;
        }
    }
}

// ============================================================================
extern "C" void kernel_launch(void* const* d_in, const int* in_sizes, int n_in,
                              void* d_out, int out_size) {
    const float* x = (const float*)d_in[0];   // (4, 2048, 4096) fp32
    const float* w = (const float*)d_in[1];   // (16384, 4096) fp32
    float* out = (float*)d_out;               // (4, 2048, 16384) fp32
    (void)in_sizes; (void)n_in; (void)out_size;

    cudaFuncSetAttribute(bitlinear_gemm, cudaFuncAttributeMaxDynamicSharedMemorySize, GEMM_SMEM);

    wabs_partial<<<2048, 256>>>(w);
    wscale_finalize<<<1, 256>>>();
    quant_wx_kernel<<<WQ_BLOCKS + DIM_M, 256>>>(w, x);

    const int grid = (DIM_M / BM) * (DIM_N / BN);  // 64 * 64 = 4096
    bitlinear_gemm<<<grid, GEMM_THREADS, GEMM_SMEM>>>(out);
}